// round 4
// baseline (speedup 1.0000x reference)
#include <cuda_runtime.h>
#include <math.h>

#define D_MODEL 1024
#define NHEADS  16
#define DK      64
#define BATCH   2
#define SEQ     2048
#define MROWS   (BATCH*SEQ)   // 4096

// Scratch (device globals: allocation-free per harness rules)
__device__ float g_Q[MROWS * D_MODEL];
__device__ float g_K[MROWS * D_MODEL];
__device__ float g_V[MROWS * D_MODEL];
__device__ float g_O[MROWS * D_MODEL];

// ---------------------------------------------------------------------------
// tf32 helpers
// ---------------------------------------------------------------------------
__device__ __forceinline__ unsigned f2tf32(float x) {
    unsigned u;
    asm("cvt.rna.tf32.f32 %0, %1;" : "=r"(u) : "f"(x));
    return u;
}
__device__ __forceinline__ float ex2f(float x) {
    float r;
    asm("ex2.approx.f32 %0, %1;" : "=f"(r) : "f"(x));
    return r;
}
// D = A*B + D, m16n8k8, A row-major, B col-major, fp32 accum
__device__ __forceinline__ void mma_tf32(float* c, const unsigned* a, const unsigned* b) {
    asm volatile(
        "mma.sync.aligned.m16n8k8.row.col.f32.tf32.tf32.f32 "
        "{%0,%1,%2,%3}, {%4,%5,%6,%7}, {%8,%9}, {%0,%1,%2,%3};\n"
        : "+f"(c[0]), "+f"(c[1]), "+f"(c[2]), "+f"(c[3])
        : "r"(a[0]), "r"(a[1]), "r"(a[2]), "r"(a[3]),
          "r"(b[0]), "r"(b[1]));
}

// ---------------------------------------------------------------------------
// tf32 GEMM: C[M,N] = A[M,K] * B[N,K]^T
// 128x128 block, BK=16, 256 threads (8 warps, 2Mx4N), warp tile 64x32.
// Smem k-major, stride 136 -> all fragment loads conflict-free ((8t+g)%32).
// ---------------------------------------------------------------------------
#define GSTR 136

__global__ __launch_bounds__(256)
void gemm_tf32(const float* __restrict__ A, const float* __restrict__ Bm,
               float* __restrict__ C, int M, int N, int K)
{
    __shared__ unsigned As[2][16 * GSTR];
    __shared__ unsigned Bs[2][16 * GSTR];

    const int tid  = threadIdx.x;
    const int warp = tid >> 5;
    const int lane = tid & 31;
    const int g    = lane >> 2;       // 0..7
    const int t    = lane & 3;        // 0..3
    const int wy   = warp & 1;        // M dir (2)
    const int wx   = warp >> 1;       // N dir (4)

    const float* Ab = A  + (size_t)blockIdx.y * 128 * K;
    const float* Bb = Bm + (size_t)blockIdx.x * 128 * K;

    const int lr = tid >> 2;          // 0..63
    const int lc = (tid & 3) * 4;     // 0,4,8,12

    float c[4][4][4];
#pragma unroll
    for (int mi = 0; mi < 4; mi++)
#pragma unroll
        for (int ni = 0; ni < 4; ni++)
#pragma unroll
            for (int r = 0; r < 4; r++) c[mi][ni][r] = 0.f;

    // Prologue: tile 0 -> buffer 0
#pragma unroll
    for (int l = 0; l < 2; l++) {
        int r = lr + l * 64;
        float4 va = *(const float4*)(Ab + (size_t)r * K + lc);
        As[0][(lc + 0) * GSTR + r] = f2tf32(va.x);
        As[0][(lc + 1) * GSTR + r] = f2tf32(va.y);
        As[0][(lc + 2) * GSTR + r] = f2tf32(va.z);
        As[0][(lc + 3) * GSTR + r] = f2tf32(va.w);
        float4 vb = *(const float4*)(Bb + (size_t)r * K + lc);
        Bs[0][(lc + 0) * GSTR + r] = f2tf32(vb.x);
        Bs[0][(lc + 1) * GSTR + r] = f2tf32(vb.y);
        Bs[0][(lc + 2) * GSTR + r] = f2tf32(vb.z);
        Bs[0][(lc + 3) * GSTR + r] = f2tf32(vb.w);
    }
    __syncthreads();

    for (int kk = 0; kk < K; kk += 16) {
        const int buf = (kk >> 4) & 1;
        const bool pf = (kk + 16) < K;

        float4 nva[2], nvb[2];
        if (pf) {
#pragma unroll
            for (int l = 0; l < 2; l++) {
                int r = lr + l * 64;
                nva[l] = *(const float4*)(Ab + (size_t)r * K + kk + 16 + lc);
                nvb[l] = *(const float4*)(Bb + (size_t)r * K + kk + 16 + lc);
            }
        }

#pragma unroll
        for (int ks = 0; ks < 16; ks += 8) {
            const int k0 = ks + t;
            unsigned a[4][4], b[4][2];
#pragma unroll
            for (int mi = 0; mi < 4; mi++) {
                int r = wy * 64 + mi * 16 + g;
                a[mi][0] = As[buf][k0 * GSTR + r];
                a[mi][1] = As[buf][k0 * GSTR + r + 8];
                a[mi][2] = As[buf][(k0 + 4) * GSTR + r];
                a[mi][3] = As[buf][(k0 + 4) * GSTR + r + 8];
            }
#pragma unroll
            for (int ni = 0; ni < 4; ni++) {
                int n = wx * 32 + ni * 8 + g;
                b[ni][0] = Bs[buf][k0 * GSTR + n];
                b[ni][1] = Bs[buf][(k0 + 4) * GSTR + n];
            }
#pragma unroll
            for (int mi = 0; mi < 4; mi++)
#pragma unroll
                for (int ni = 0; ni < 4; ni++)
                    mma_tf32(c[mi][ni], a[mi], b[ni]);
        }

        if (pf) {
            const int nb = buf ^ 1;
#pragma unroll
            for (int l = 0; l < 2; l++) {
                int r = lr + l * 64;
                As[nb][(lc + 0) * GSTR + r] = f2tf32(nva[l].x);
                As[nb][(lc + 1) * GSTR + r] = f2tf32(nva[l].y);
                As[nb][(lc + 2) * GSTR + r] = f2tf32(nva[l].z);
                As[nb][(lc + 3) * GSTR + r] = f2tf32(nva[l].w);
                Bs[nb][(lc + 0) * GSTR + r] = f2tf32(nvb[l].x);
                Bs[nb][(lc + 1) * GSTR + r] = f2tf32(nvb[l].y);
                Bs[nb][(lc + 2) * GSTR + r] = f2tf32(nvb[l].z);
                Bs[nb][(lc + 3) * GSTR + r] = f2tf32(nvb[l].w);
            }
        }
        __syncthreads();
    }

    // Epilogue
#pragma unroll
    for (int mi = 0; mi < 4; mi++) {
        int row = blockIdx.y * 128 + wy * 64 + mi * 16 + g;
#pragma unroll
        for (int ni = 0; ni < 4; ni++) {
            int col = blockIdx.x * 128 + wx * 32 + ni * 8 + 2 * t;
            *(float2*)(C + (size_t)row * N + col) =
                make_float2(c[mi][ni][0], c[mi][ni][1]);
            *(float2*)(C + (size_t)(row + 8) * N + col) =
                make_float2(c[mi][ni][2], c[mi][ni][3]);
        }
    }
}

// ---------------------------------------------------------------------------
// Flash attention, tf32 tensor cores. Br=Bc=128, dk=64, 256 threads.
// Each warp owns 16 q-rows end-to-end. Softmax in exp2 domain.
// ---------------------------------------------------------------------------
#define QSTR 136
#define VSTR 72

__global__ __launch_bounds__(256)
void attn_fwd(const float* __restrict__ Q, const float* __restrict__ K,
              const float* __restrict__ V, float* __restrict__ O)
{
    extern __shared__ unsigned sm[];
    unsigned* Qs = sm;                   // [64][136] k-major
    unsigned* Ks = Qs + 64 * QSTR;       // [64][136] k-major
    unsigned* Vs = Ks + 64 * QSTR;       // [128][72] row-major
    unsigned* Ps = Vs + 128 * VSTR;      // [128][136] row-major (warp-private bands)

    const int qb = (gridDim.x - 1) - blockIdx.x;  // heavy blocks first
    const int h  = blockIdx.y;
    const int b  = blockIdx.z;
    const int tid  = threadIdx.x;
    const int warp = tid >> 5;
    const int lane = tid & 31;
    const int g    = lane >> 2;
    const int t    = lane & 3;

    const size_t base = (size_t)b * SEQ * D_MODEL + (size_t)h * DK;
    const float* Qg = Q + base + (size_t)qb * 128 * D_MODEL;
    // fold 1/sqrt(dk) and log2(e) into Q so softmax runs in exp2 domain
    const float qscale = 0.125f * 1.4426950408889634f;

    // Load Q tile (128 x 64) k-major, prescaled, tf32
#pragma unroll
    for (int l = 0; l < 8; l++) {
        int idx = tid + l * 256;
        int r = idx >> 4;                // 0..127
        int cc = (idx & 15) * 4;         // 0..60
        float4 v = *(const float4*)(Qg + (size_t)r * D_MODEL + cc);
        Qs[(cc + 0) * QSTR + r] = f2tf32(v.x * qscale);
        Qs[(cc + 1) * QSTR + r] = f2tf32(v.y * qscale);
        Qs[(cc + 2) * QSTR + r] = f2tf32(v.z * qscale);
        Qs[(cc + 3) * QSTR + r] = f2tf32(v.w * qscale);
    }
    __syncthreads();

    // Preload Q fragments for this warp's 16 rows (held all kernel)
    unsigned qa[8][4];
    const int rq = warp * 16 + g;
#pragma unroll
    for (int kt = 0; kt < 8; kt++) {
        int k0 = kt * 8 + t;
        qa[kt][0] = Qs[k0 * QSTR + rq];
        qa[kt][1] = Qs[k0 * QSTR + rq + 8];
        qa[kt][2] = Qs[(k0 + 4) * QSTR + rq];
        qa[kt][3] = Qs[(k0 + 4) * QSTR + rq + 8];
    }

    float m0 = -1e30f, m1 = -1e30f, l0 = 0.f, l1 = 0.f;
    float o[8][4];
#pragma unroll
    for (int ni = 0; ni < 8; ni++)
#pragma unroll
        for (int r = 0; r < 4; r++) o[ni][r] = 0.f;

    const int prow0 = warp * 16 + g;
    const int prow1 = prow0 + 8;

    for (int j = 0; j <= qb; j++) {
        const float* Kg = K + base + (size_t)j * 128 * D_MODEL;
        const float* Vg = V + base + (size_t)j * 128 * D_MODEL;
#pragma unroll
        for (int l = 0; l < 8; l++) {
            int idx = tid + l * 256;
            int r = idx >> 4;
            int cc = (idx & 15) * 4;
            float4 vk = *(const float4*)(Kg + (size_t)r * D_MODEL + cc);
            Ks[(cc + 0) * QSTR + r] = f2tf32(vk.x);
            Ks[(cc + 1) * QSTR + r] = f2tf32(vk.y);
            Ks[(cc + 2) * QSTR + r] = f2tf32(vk.z);
            Ks[(cc + 3) * QSTR + r] = f2tf32(vk.w);
            float4 vv = *(const float4*)(Vg + (size_t)r * D_MODEL + cc);
            Vs[r * VSTR + cc + 0] = f2tf32(vv.x);
            Vs[r * VSTR + cc + 1] = f2tf32(vv.y);
            Vs[r * VSTR + cc + 2] = f2tf32(vv.z);
            Vs[r * VSTR + cc + 3] = f2tf32(vv.w);
        }
        __syncthreads();

        // ---- S = Q * K^T : 16 n-tiles x 8 k-tiles of m16n8k8 ----
        float s[16][4];
#pragma unroll
        for (int ni = 0; ni < 16; ni++) {
            s[ni][0] = 0.f; s[ni][1] = 0.f; s[ni][2] = 0.f; s[ni][3] = 0.f;
            int n = ni * 8 + g;
#pragma unroll
            for (int kt = 0; kt < 8; kt++) {
                int k0 = kt * 8 + t;
                unsigned bb[2];
                bb[0] = Ks[k0 * QSTR + n];
                bb[1] = Ks[(k0 + 4) * QSTR + n];
                mma_tf32(s[ni], qa[kt], bb);
            }
        }

        // Causal mask (diagonal block only); relative row/col comparison
        if (j == qb) {
#pragma unroll
            for (int ni = 0; ni < 16; ni++) {
                int cb = ni * 8 + 2 * t;
                if (cb     > prow0) s[ni][0] = -1e30f;
                if (cb + 1 > prow0) s[ni][1] = -1e30f;
                if (cb     > prow1) s[ni][2] = -1e30f;
                if (cb + 1 > prow1) s[ni][3] = -1e30f;
            }
        }

        // ---- Online softmax (exp2 domain). Rows g / g+8; quad = 4 lanes ----
        float rm0 = -1e30f, rm1 = -1e30f;
#pragma unroll
        for (int ni = 0; ni < 16; ni++) {
            rm0 = fmaxf(rm0, fmaxf(s[ni][0], s[ni][1]));
            rm1 = fmaxf(rm1, fmaxf(s[ni][2], s[ni][3]));
        }
        rm0 = fmaxf(rm0, __shfl_xor_sync(0xffffffffu, rm0, 1));
        rm0 = fmaxf(rm0, __shfl_xor_sync(0xffffffffu, rm0, 2));
        rm1 = fmaxf(rm1, __shfl_xor_sync(0xffffffffu, rm1, 1));
        rm1 = fmaxf(rm1, __shfl_xor_sync(0xffffffffu, rm1, 2));

        float mn0 = fmaxf(m0, rm0), mn1 = fmaxf(m1, rm1);
        float a0 = ex2f(m0 - mn0), a1 = ex2f(m1 - mn1);
        float rs0 = 0.f, rs1 = 0.f;
#pragma unroll
        for (int ni = 0; ni < 16; ni++) {
            int col = ni * 8 + 2 * t;
            float p00 = ex2f(s[ni][0] - mn0);
            float p01 = ex2f(s[ni][1] - mn0);
            float p10 = ex2f(s[ni][2] - mn1);
            float p11 = ex2f(s[ni][3] - mn1);
            rs0 += p00 + p01;
            rs1 += p10 + p11;
            Ps[prow0 * QSTR + col]     = f2tf32(p00);
            Ps[prow0 * QSTR + col + 1] = f2tf32(p01);
            Ps[prow1 * QSTR + col]     = f2tf32(p10);
            Ps[prow1 * QSTR + col + 1] = f2tf32(p11);
        }
        rs0 += __shfl_xor_sync(0xffffffffu, rs0, 1);
        rs0 += __shfl_xor_sync(0xffffffffu, rs0, 2);
        rs1 += __shfl_xor_sync(0xffffffffu, rs1, 1);
        rs1 += __shfl_xor_sync(0xffffffffu, rs1, 2);
        l0 = l0 * a0 + rs0;  m0 = mn0;
        l1 = l1 * a1 + rs1;  m1 = mn1;
#pragma unroll
        for (int ni = 0; ni < 8; ni++) {
            o[ni][0] *= a0; o[ni][1] *= a0;
            o[ni][2] *= a1; o[ni][3] *= a1;
        }
        __syncwarp();   // P band is warp-private: warp-level ordering suffices

        // ---- O += P * V : 16 k-tiles x 8 n-tiles ----
#pragma unroll
        for (int kt = 0; kt < 16; kt++) {
            int k0 = kt * 8 + t;
            unsigned pa[4];
            pa[0] = Ps[prow0 * QSTR + k0];
            pa[1] = Ps[prow1 * QSTR + k0];
            pa[2] = Ps[prow0 * QSTR + k0 + 4];
            pa[3] = Ps[prow1 * QSTR + k0 + 4];
#pragma unroll
            for (int ni = 0; ni < 8; ni++) {
                unsigned vb[2];
                int n = ni * 8 + g;
                vb[0] = Vs[k0 * VSTR + n];
                vb[1] = Vs[(k0 + 4) * VSTR + n];
                mma_tf32(o[ni], pa, vb);
            }
        }
        __syncthreads();  // protect Ks/Vs before next iteration's loads
    }

    // Normalize and write O
    float inv0 = 1.f / l0, inv1 = 1.f / l1;
    float* Og = O + base + (size_t)qb * 128 * D_MODEL;
#pragma unroll
    for (int ni = 0; ni < 8; ni++) {
        int col = ni * 8 + 2 * t;
        *(float2*)(Og + (size_t)prow0 * D_MODEL + col) =
            make_float2(o[ni][0] * inv0, o[ni][1] * inv0);
        *(float2*)(Og + (size_t)prow1 * D_MODEL + col) =
            make_float2(o[ni][2] * inv1, o[ni][3] * inv1);
    }
}

// ---------------------------------------------------------------------------
// kernel_launch
// ---------------------------------------------------------------------------
extern "C" void kernel_launch(void* const* d_in, const int* in_sizes, int n_in,
                              void* d_out, int out_size)
{
    const float* x  = (const float*)d_in[0];
    const float* wq = (const float*)d_in[1];
    const float* wk = (const float*)d_in[2];
    const float* wv = (const float*)d_in[3];
    const float* wo = (const float*)d_in[4];
    float* out = (float*)d_out;

    float *q, *k, *v, *o;
    cudaGetSymbolAddress((void**)&q, g_Q);
    cudaGetSymbolAddress((void**)&k, g_K);
    cudaGetSymbolAddress((void**)&v, g_V);
    cudaGetSymbolAddress((void**)&o, g_O);

    dim3 gg(D_MODEL / 128, MROWS / 128);   // (8, 32)
    gemm_tf32<<<gg, 256>>>(x, wq, q, MROWS, D_MODEL, D_MODEL);
    gemm_tf32<<<gg, 256>>>(x, wk, k, MROWS, D_MODEL, D_MODEL);
    gemm_tf32<<<gg, 256>>>(x, wv, v, MROWS, D_MODEL, D_MODEL);

    const int smem_bytes = (64 * QSTR * 2 + 128 * VSTR + 128 * QSTR) * 4; // 176,128 B
    cudaFuncSetAttribute(attn_fwd, cudaFuncAttributeMaxDynamicSharedMemorySize,
                         smem_bytes);
    dim3 ga(SEQ / 128, NHEADS, BATCH);     // (16, 16, 2)
    attn_fwd<<<ga, 256, smem_bytes>>>(q, k, v, o);

    gemm_tf32<<<gg, 256>>>(o, wo, out, MROWS, D_MODEL, D_MODEL);
}

// round 5
// speedup vs baseline: 1.1140x; 1.1140x over previous
#include <cuda_runtime.h>
#include <cuda_bf16.h>

#define D_MODEL 1024
#define NHEADS  16
#define DK      64
#define BATCH   2
#define SEQ     2048
#define MROWS   (BATCH*SEQ)   // 4096

// Scratch (device globals; allocation-free per harness rules).
// Q/K packed bf16x2 hi/lo: [b][h][s][32 words of dk-pairs]
// Vt packed bf16x2 hi/lo, transposed: [b][h][dk][1024 words of s-pairs]
__device__ unsigned g_Qh[(size_t)BATCH*NHEADS*SEQ*32];
__device__ unsigned g_Ql[(size_t)BATCH*NHEADS*SEQ*32];
__device__ unsigned g_Kh[(size_t)BATCH*NHEADS*SEQ*32];
__device__ unsigned g_Kl[(size_t)BATCH*NHEADS*SEQ*32];
__device__ float    g_V [(size_t)MROWS*D_MODEL];
__device__ unsigned g_Vth[(size_t)BATCH*NHEADS*DK*(SEQ/2)];
__device__ unsigned g_Vtl[(size_t)BATCH*NHEADS*DK*(SEQ/2)];
__device__ float    g_O [(size_t)MROWS*D_MODEL];

// ---------------------------------------------------------------------------
__device__ __forceinline__ float ex2f(float x) {
    float r; asm("ex2.approx.f32 %0, %1;" : "=f"(r) : "f"(x)); return r;
}
__device__ __forceinline__ unsigned pack2(float x, float y) {
    __nv_bfloat162 h = __floats2bfloat162_rn(x, y);
    return reinterpret_cast<unsigned&>(h);
}
__device__ __forceinline__ void split2(float x, float y, unsigned& hi, unsigned& lo) {
    __nv_bfloat162 h = __floats2bfloat162_rn(x, y);
    float xr = x - __bfloat162float(h.x);
    float yr = y - __bfloat162float(h.y);
    hi = reinterpret_cast<unsigned&>(h);
    lo = pack2(xr, yr);
}
__device__ __forceinline__ void mma_bf16(float* c, const unsigned* a, const unsigned* b) {
    asm volatile(
        "mma.sync.aligned.m16n8k16.row.col.f32.bf16.bf16.f32 "
        "{%0,%1,%2,%3}, {%4,%5,%6,%7}, {%8,%9}, {%0,%1,%2,%3};\n"
        : "+f"(c[0]), "+f"(c[1]), "+f"(c[2]), "+f"(c[3])
        : "r"(a[0]), "r"(a[1]), "r"(a[2]), "r"(a[3]), "r"(b[0]), "r"(b[1]));
}
__device__ __forceinline__ void cpa16(unsigned dst, const unsigned* src) {
    asm volatile("cp.async.cg.shared.global [%0], [%1], 16;\n" :: "r"(dst), "l"(src) : "memory");
}
__device__ __forceinline__ void cpa_commit() { asm volatile("cp.async.commit_group;\n" ::: "memory"); }
__device__ __forceinline__ void cpa_wait0()  { asm volatile("cp.async.wait_group 0;\n" ::: "memory"); }

// ---------------------------------------------------------------------------
// bf16x3 GEMM mainloop: C[256x128] = A[256x1024] * B[128x1024]^T, BK=16.
// 256 threads = 8 warps (4M x 2N), warp tile 64x64.
// ---------------------------------------------------------------------------
#define AW 12
#define GEMM_SMEM_BYTES ((2*256*AW*2 + 2*128*AW*2) * 4)   // 73728

__device__ __forceinline__ void gemm_main(const float* __restrict__ Ab,
                                          const float* __restrict__ Bb,
                                          float (&c)[4][8][4], unsigned* sm)
{
    unsigned* Ash = sm;
    unsigned* Asl = sm + 2*256*AW;
    unsigned* Bsh = sm + 4*256*AW;
    unsigned* Bsl = sm + 4*256*AW + 2*128*AW;

    const int tid  = threadIdx.x;
    const int warp = tid >> 5, lane = tid & 31;
    const int g = lane >> 2, t = lane & 3;
    const int wy = warp >> 1, wx = warp & 1;
    const int lr = tid >> 2;
    const int lc = (tid & 3) * 4;
    const int lw = lc >> 1;

#pragma unroll
    for (int mi = 0; mi < 4; mi++)
#pragma unroll
        for (int ni = 0; ni < 8; ni++)
#pragma unroll
            for (int r = 0; r < 4; r++) c[mi][ni][r] = 0.f;

#pragma unroll
    for (int l = 0; l < 4; l++) {
        int r = lr + l * 64;
        float4 v = *(const float4*)(Ab + (size_t)r * 1024 + lc);
        unsigned h0, l0, h1, l1;
        split2(v.x, v.y, h0, l0); split2(v.z, v.w, h1, l1);
        Ash[r*AW + lw] = h0; Ash[r*AW + lw + 1] = h1;
        Asl[r*AW + lw] = l0; Asl[r*AW + lw + 1] = l1;
    }
#pragma unroll
    for (int l = 0; l < 2; l++) {
        int r = lr + l * 64;
        float4 v = *(const float4*)(Bb + (size_t)r * 1024 + lc);
        unsigned h0, l0, h1, l1;
        split2(v.x, v.y, h0, l0); split2(v.z, v.w, h1, l1);
        Bsh[r*AW + lw] = h0; Bsh[r*AW + lw + 1] = h1;
        Bsl[r*AW + lw] = l0; Bsl[r*AW + lw + 1] = l1;
    }
    __syncthreads();

    for (int kk = 0; kk < 1024; kk += 16) {
        const int buf = (kk >> 4) & 1;
        const bool pf = (kk + 16) < 1024;
        const unsigned* Ah = Ash + buf * 256*AW;
        const unsigned* Al = Asl + buf * 256*AW;
        const unsigned* Bh = Bsh + buf * 128*AW;
        const unsigned* Bl = Bsl + buf * 128*AW;

        float4 pa[4], pb[2];
        if (pf) {
#pragma unroll
            for (int l = 0; l < 4; l++)
                pa[l] = *(const float4*)(Ab + (size_t)(lr + l*64) * 1024 + kk + 16 + lc);
#pragma unroll
            for (int l = 0; l < 2; l++)
                pb[l] = *(const float4*)(Bb + (size_t)(lr + l*64) * 1024 + kk + 16 + lc);
        }

        unsigned bh[8][2], bl[8][2];
#pragma unroll
        for (int ni = 0; ni < 8; ni++) {
            int n = wx * 64 + ni * 8 + g;
            bh[ni][0] = Bh[n*AW + t];   bh[ni][1] = Bh[n*AW + 4 + t];
            bl[ni][0] = Bl[n*AW + t];   bl[ni][1] = Bl[n*AW + 4 + t];
        }
#pragma unroll
        for (int mi = 0; mi < 4; mi++) {
            int rr = wy * 64 + mi * 16 + g;
            unsigned ah[4], al[4];
            ah[0] = Ah[rr*AW + t];     ah[1] = Ah[(rr+8)*AW + t];
            ah[2] = Ah[rr*AW + 4 + t]; ah[3] = Ah[(rr+8)*AW + 4 + t];
            al[0] = Al[rr*AW + t];     al[1] = Al[(rr+8)*AW + t];
            al[2] = Al[rr*AW + 4 + t]; al[3] = Al[(rr+8)*AW + 4 + t];
#pragma unroll
            for (int ni = 0; ni < 8; ni++) {
                mma_bf16(c[mi][ni], ah, bh[ni]);
                mma_bf16(c[mi][ni], ah, bl[ni]);
                mma_bf16(c[mi][ni], al, bh[ni]);
            }
        }

        if (pf) {
            const int nb = buf ^ 1;
            unsigned* nAh = Ash + nb * 256*AW;  unsigned* nAl = Asl + nb * 256*AW;
            unsigned* nBh = Bsh + nb * 128*AW;  unsigned* nBl = Bsl + nb * 128*AW;
#pragma unroll
            for (int l = 0; l < 4; l++) {
                int r = lr + l * 64;
                unsigned h0, l0, h1, l1;
                split2(pa[l].x, pa[l].y, h0, l0); split2(pa[l].z, pa[l].w, h1, l1);
                nAh[r*AW + lw] = h0; nAh[r*AW + lw + 1] = h1;
                nAl[r*AW + lw] = l0; nAl[r*AW + lw + 1] = l1;
            }
#pragma unroll
            for (int l = 0; l < 2; l++) {
                int r = lr + l * 64;
                unsigned h0, l0, h1, l1;
                split2(pb[l].x, pb[l].y, h0, l0); split2(pb[l].z, pb[l].w, h1, l1);
                nBh[r*AW + lw] = h0; nBh[r*AW + lw + 1] = h1;
                nBl[r*AW + lw] = l0; nBl[r*AW + lw + 1] = l1;
            }
        }
        __syncthreads();
    }
}

// z=0 -> Q packed (prescaled), z=1 -> K packed, z=2 -> V f32
__global__ __launch_bounds__(256, 1)
void qkv_gemm(const float* __restrict__ X, const float* __restrict__ Wq,
              const float* __restrict__ Wk, const float* __restrict__ Wv)
{
    extern __shared__ unsigned gsm[];
    const int z = blockIdx.z;
    const float* Bm = (z == 0) ? Wq : (z == 1) ? Wk : Wv;
    const float* Ab = X  + (size_t)blockIdx.y * 256 * 1024;
    const float* Bb = Bm + (size_t)blockIdx.x * 128 * 1024;

    float c[4][8][4];
    gemm_main(Ab, Bb, c, gsm);

    const int tid  = threadIdx.x;
    const int warp = tid >> 5, lane = tid & 31;
    const int g = lane >> 2, t = lane & 3;
    const int wy = warp >> 1, wx = warp & 1;

    if (z < 2) {
        unsigned* Ph = z ? g_Kh : g_Qh;
        unsigned* Pl = z ? g_Kl : g_Ql;
        const float scale = z ? 1.f : 0.125f * 1.4426950408889634f;
#pragma unroll
        for (int mi = 0; mi < 4; mi++) {
            int row = blockIdx.y * 256 + wy * 64 + mi * 16 + g;
            int bb = row >> 11, s = row & 2047;
#pragma unroll
            for (int ni = 0; ni < 8; ni++) {
                int col = blockIdx.x * 128 + wx * 64 + ni * 8 + 2 * t;
                int hh = col >> 6, dkw = (col & 63) >> 1;
                size_t w = (((size_t)bb * NHEADS + hh) * SEQ + s) * 32 + dkw;
                unsigned hi, lo;
                split2(c[mi][ni][0] * scale, c[mi][ni][1] * scale, hi, lo);
                Ph[w] = hi; Pl[w] = lo;
                split2(c[mi][ni][2] * scale, c[mi][ni][3] * scale, hi, lo);
                Ph[w + 8*32] = hi; Pl[w + 8*32] = lo;
            }
        }
    } else {
#pragma unroll
        for (int mi = 0; mi < 4; mi++) {
            int row = blockIdx.y * 256 + wy * 64 + mi * 16 + g;
#pragma unroll
            for (int ni = 0; ni < 8; ni++) {
                int col = blockIdx.x * 128 + wx * 64 + ni * 8 + 2 * t;
                *(float2*)&g_V[(size_t)row * 1024 + col] =
                    make_float2(c[mi][ni][0], c[mi][ni][1]);
                *(float2*)&g_V[(size_t)(row + 8) * 1024 + col] =
                    make_float2(c[mi][ni][2], c[mi][ni][3]);
            }
        }
    }
}

__global__ __launch_bounds__(256, 1)
void proj_gemm(const float* __restrict__ Wo, float* __restrict__ Out)
{
    extern __shared__ unsigned gsm[];
    const float* Ab = g_O + (size_t)blockIdx.y * 256 * 1024;
    const float* Bb = Wo  + (size_t)blockIdx.x * 128 * 1024;

    float c[4][8][4];
    gemm_main(Ab, Bb, c, gsm);

    const int tid  = threadIdx.x;
    const int warp = tid >> 5, lane = tid & 31;
    const int g = lane >> 2, t = lane & 3;
    const int wy = warp >> 1, wx = warp & 1;
#pragma unroll
    for (int mi = 0; mi < 4; mi++) {
        int row = blockIdx.y * 256 + wy * 64 + mi * 16 + g;
#pragma unroll
        for (int ni = 0; ni < 8; ni++) {
            int col = blockIdx.x * 128 + wx * 64 + ni * 8 + 2 * t;
            *(float2*)&Out[(size_t)row * 1024 + col] =
                make_float2(c[mi][ni][0], c[mi][ni][1]);
            *(float2*)&Out[(size_t)(row + 8) * 1024 + col] =
                make_float2(c[mi][ni][2], c[mi][ni][3]);
        }
    }
}

// V transpose + split: g_V [b,s,h*64+dk] -> g_Vt{h,l} [b,h][dk][s/2 words]
__global__ __launch_bounds__(256)
void vtrans()
{
    __shared__ float smv[128 * 65];
    const int sc = blockIdx.x, h = blockIdx.y, b = blockIdx.z;
    const int tid = threadIdx.x;
    const float* src = g_V + ((size_t)b * SEQ + sc * 128) * D_MODEL + h * DK;
#pragma unroll
    for (int l = 0; l < 8; l++) {
        int idx = tid + l * 256;
        int r = idx >> 4, cc = (idx & 15) * 4;
        float4 v = *(const float4*)(src + (size_t)r * D_MODEL + cc);
        smv[r*65 + cc] = v.x; smv[r*65 + cc + 1] = v.y;
        smv[r*65 + cc + 2] = v.z; smv[r*65 + cc + 3] = v.w;
    }
    __syncthreads();
    const size_t dbase = ((size_t)(b * NHEADS + h) * DK) * 1024 + sc * 64;
#pragma unroll
    for (int l = 0; l < 16; l++) {
        int idx = tid + l * 256;
        int dk = idx >> 6, sw = idx & 63;
        unsigned hi, lo;
        split2(smv[(2*sw) * 65 + dk], smv[(2*sw + 1) * 65 + dk], hi, lo);
        g_Vth[dbase + (size_t)dk * 1024 + sw] = hi;
        g_Vtl[dbase + (size_t)dk * 1024 + sw] = lo;
    }
}

// ---------------------------------------------------------------------------
// Flash attention, bf16x3, cp.async double-buffered K/V, P in registers.
// ---------------------------------------------------------------------------
#define KWS 36
#define VWS 68
#define ATTN_SMEM_BYTES ((2*128*KWS*2 + 2*64*VWS*2) * 4)   // 143360

__global__ __launch_bounds__(256, 1)
void attn_fwd()
{
    extern __shared__ unsigned sm[];
    unsigned* Ksh = sm;
    unsigned* Ksl = Ksh + 2*128*KWS;
    unsigned* Vsh = Ksl + 2*128*KWS;
    unsigned* Vsl = Vsh + 2*64*VWS;
    const unsigned smb  = (unsigned)__cvta_generic_to_shared(sm);
    const unsigned KshB = smb;
    const unsigned KslB = smb + 2*128*KWS*4;
    const unsigned VshB = KslB + 2*128*KWS*4;
    const unsigned VslB = VshB + 2*64*VWS*4;

    const int qb = (gridDim.x - 1) - blockIdx.x;
    const int bh = blockIdx.z * NHEADS + blockIdx.y;
    const int tid = threadIdx.x, warp = tid >> 5, lane = tid & 31;
    const int g = lane >> 2, t = lane & 3;
    const int kr0 = tid >> 3, kch = (tid & 7) * 4;
    const int vd0 = tid >> 4, vch = (tid & 15) * 4;

    auto load_kv = [&](int buf, int j) {
        const size_t kbase = ((size_t)bh * SEQ + (size_t)j * 128) * 32;
#pragma unroll
        for (int l = 0; l < 4; l++) {
            int r = kr0 + l * 32;
            unsigned doff = (unsigned)((r * KWS + kch) * 4);
            cpa16(KshB + buf*(128*KWS*4) + doff, g_Kh + kbase + r*32 + kch);
            cpa16(KslB + buf*(128*KWS*4) + doff, g_Kl + kbase + r*32 + kch);
        }
        const size_t vbase = (size_t)bh * DK * 1024 + (size_t)j * 64;
#pragma unroll
        for (int l = 0; l < 4; l++) {
            int dk = vd0 + l * 16;
            unsigned doff = (unsigned)((dk * VWS + vch) * 4);
            cpa16(VshB + buf*(64*VWS*4) + doff, g_Vth + vbase + (size_t)dk*1024 + vch);
            cpa16(VslB + buf*(64*VWS*4) + doff, g_Vtl + vbase + (size_t)dk*1024 + vch);
        }
        cpa_commit();
    };

    load_kv(0, 0);

    unsigned qh[4][4], ql[4][4];
    {
        const size_t qbase = ((size_t)bh * SEQ + (size_t)qb * 128 + warp * 16 + g) * 32;
#pragma unroll
        for (int kt = 0; kt < 4; kt++) {
            qh[kt][0] = g_Qh[qbase + kt*8 + t];
            qh[kt][1] = g_Qh[qbase + 8*32 + kt*8 + t];
            qh[kt][2] = g_Qh[qbase + kt*8 + 4 + t];
            qh[kt][3] = g_Qh[qbase + 8*32 + kt*8 + 4 + t];
            ql[kt][0] = g_Ql[qbase + kt*8 + t];
            ql[kt][1] = g_Ql[qbase + 8*32 + kt*8 + t];
            ql[kt][2] = g_Ql[qbase + kt*8 + 4 + t];
            ql[kt][3] = g_Ql[qbase + 8*32 + kt*8 + 4 + t];
        }
    }

    float m0 = -1e30f, m1 = -1e30f, l0 = 0.f, l1 = 0.f;
    float o[8][4];
#pragma unroll
    for (int ni = 0; ni < 8; ni++)
#pragma unroll
        for (int r = 0; r < 4; r++) o[ni][r] = 0.f;

    const int prow0 = warp * 16 + g;
    const int prow1 = prow0 + 8;

    cpa_wait0();
    __syncthreads();

    int buf = 0;
    for (int j = 0; j <= qb; j++) {
        if (j < qb) load_kv(buf ^ 1, j + 1);

        const unsigned* Kh_t = Ksh + buf * 128*KWS;
        const unsigned* Kl_t = Ksl + buf * 128*KWS;
        const unsigned* Vh_t = Vsh + buf * 64*VWS;
        const unsigned* Vl_t = Vsl + buf * 64*VWS;

        float s[16][4];
#pragma unroll
        for (int ni = 0; ni < 16; ni++) {
            s[ni][0] = 0.f; s[ni][1] = 0.f; s[ni][2] = 0.f; s[ni][3] = 0.f;
            int n = ni * 8 + g;
#pragma unroll
            for (int kt = 0; kt < 4; kt++) {
                unsigned bh2[2], bl2[2];
                bh2[0] = Kh_t[n*KWS + kt*8 + t];
                bh2[1] = Kh_t[n*KWS + kt*8 + 4 + t];
                bl2[0] = Kl_t[n*KWS + kt*8 + t];
                bl2[1] = Kl_t[n*KWS + kt*8 + 4 + t];
                mma_bf16(s[ni], qh[kt], bh2);
                mma_bf16(s[ni], qh[kt], bl2);
                mma_bf16(s[ni], ql[kt], bh2);
            }
        }

        if (j == qb) {
#pragma unroll
            for (int ni = 0; ni < 16; ni++) {
                int cb = ni * 8 + 2 * t;
                if (cb     > prow0) s[ni][0] = -1e30f;
                if (cb + 1 > prow0) s[ni][1] = -1e30f;
                if (cb     > prow1) s[ni][2] = -1e30f;
                if (cb + 1 > prow1) s[ni][3] = -1e30f;
            }
        }

        float rm0 = -1e30f, rm1 = -1e30f;
#pragma unroll
        for (int ni = 0; ni < 16; ni++) {
            rm0 = fmaxf(rm0, fmaxf(s[ni][0], s[ni][1]));
            rm1 = fmaxf(rm1, fmaxf(s[ni][2], s[ni][3]));
        }
        rm0 = fmaxf(rm0, __shfl_xor_sync(0xffffffffu, rm0, 1));
        rm0 = fmaxf(rm0, __shfl_xor_sync(0xffffffffu, rm0, 2));
        rm1 = fmaxf(rm1, __shfl_xor_sync(0xffffffffu, rm1, 1));
        rm1 = fmaxf(rm1, __shfl_xor_sync(0xffffffffu, rm1, 2));

        float mn0 = fmaxf(m0, rm0), mn1 = fmaxf(m1, rm1);
        float a0 = ex2f(m0 - mn0), a1 = ex2f(m1 - mn1);
        float rs0 = 0.f, rs1 = 0.f;
#pragma unroll
        for (int ni = 0; ni < 16; ni++) {
            s[ni][0] = ex2f(s[ni][0] - mn0);
            s[ni][1] = ex2f(s[ni][1] - mn0);
            s[ni][2] = ex2f(s[ni][2] - mn1);
            s[ni][3] = ex2f(s[ni][3] - mn1);
            rs0 += s[ni][0] + s[ni][1];
            rs1 += s[ni][2] + s[ni][3];
        }
        rs0 += __shfl_xor_sync(0xffffffffu, rs0, 1);
        rs0 += __shfl_xor_sync(0xffffffffu, rs0, 2);
        rs1 += __shfl_xor_sync(0xffffffffu, rs1, 1);
        rs1 += __shfl_xor_sync(0xffffffffu, rs1, 2);
        l0 = l0 * a0 + rs0;  m0 = mn0;
        l1 = l1 * a1 + rs1;  m1 = mn1;
#pragma unroll
        for (int ni = 0; ni < 8; ni++) {
            o[ni][0] *= a0; o[ni][1] *= a0;
            o[ni][2] *= a1; o[ni][3] *= a1;
        }

        // O += P*V, P in registers (S accum layout == A fragment layout)
#pragma unroll
        for (int kt = 0; kt < 8; kt++) {
            unsigned ph[4], pl[4];
            split2(s[2*kt][0],   s[2*kt][1],   ph[0], pl[0]);
            split2(s[2*kt][2],   s[2*kt][3],   ph[1], pl[1]);
            split2(s[2*kt+1][0], s[2*kt+1][1], ph[2], pl[2]);
            split2(s[2*kt+1][2], s[2*kt+1][3], ph[3], pl[3]);
#pragma unroll
            for (int ni = 0; ni < 8; ni++) {
                int n = ni * 8 + g;
                unsigned vh2[2], vl2[2];
                vh2[0] = Vh_t[n*VWS + kt*8 + t];
                vh2[1] = Vh_t[n*VWS + kt*8 + 4 + t];
                vl2[0] = Vl_t[n*VWS + kt*8 + t];
                vl2[1] = Vl_t[n*VWS + kt*8 + 4 + t];
                mma_bf16(o[ni], ph, vh2);
                mma_bf16(o[ni], ph, vl2);
                mma_bf16(o[ni], pl, vh2);
            }
        }

        if (j < qb) cpa_wait0();
        __syncthreads();
        buf ^= 1;
    }

    float inv0 = 1.f / l0, inv1 = 1.f / l1;
    const size_t obase = ((size_t)blockIdx.z * SEQ + (size_t)qb * 128) * D_MODEL
                       + blockIdx.y * DK;
#pragma unroll
    for (int ni = 0; ni < 8; ni++) {
        int col = ni * 8 + 2 * t;
        *(float2*)&g_O[obase + (size_t)prow0 * D_MODEL + col] =
            make_float2(o[ni][0] * inv0, o[ni][1] * inv0);
        *(float2*)&g_O[obase + (size_t)prow1 * D_MODEL + col] =
            make_float2(o[ni][2] * inv1, o[ni][3] * inv1);
    }
}

// ---------------------------------------------------------------------------
extern "C" void kernel_launch(void* const* d_in, const int* in_sizes, int n_in,
                              void* d_out, int out_size)
{
    const float* x  = (const float*)d_in[0];
    const float* wq = (const float*)d_in[1];
    const float* wk = (const float*)d_in[2];
    const float* wv = (const float*)d_in[3];
    const float* wo = (const float*)d_in[4];
    float* out = (float*)d_out;

    cudaFuncSetAttribute(qkv_gemm,  cudaFuncAttributeMaxDynamicSharedMemorySize, GEMM_SMEM_BYTES);
    cudaFuncSetAttribute(proj_gemm, cudaFuncAttributeMaxDynamicSharedMemorySize, GEMM_SMEM_BYTES);
    cudaFuncSetAttribute(attn_fwd,  cudaFuncAttributeMaxDynamicSharedMemorySize, ATTN_SMEM_BYTES);

    dim3 gq(D_MODEL / 128, MROWS / 256, 3);          // (8,16,3)
    qkv_gemm<<<gq, 256, GEMM_SMEM_BYTES>>>(x, wq, wk, wv);

    vtrans<<<dim3(SEQ / 128, NHEADS, BATCH), 256>>>();

    attn_fwd<<<dim3(SEQ / 128, NHEADS, BATCH), 256, ATTN_SMEM_BYTES>>>();

    dim3 gp(D_MODEL / 128, MROWS / 256);             // (8,16)
    proj_gemm<<<gp, 256, GEMM_SMEM_BYTES>>>(wo, out);
}